// round 12
// baseline (speedup 1.0000x reference)
#include <cuda_runtime.h>
#include <math.h>

#define NB 16
#define NS 2048
#define NIN 128

typedef unsigned long long u64;
typedef unsigned int u32;

__device__ __forceinline__ u64 f2fma(u64 a, u64 b, u64 c) {
    u64 d; asm("fma.rn.f32x2 %0,%1,%2,%3;" : "=l"(d) : "l"(a), "l"(b), "l"(c)); return d;
}
__device__ __forceinline__ u64 f2add(u64 a, u64 b) {
    u64 d; asm("add.rn.f32x2 %0,%1,%2;" : "=l"(d) : "l"(a), "l"(b)); return d;
}
__device__ __forceinline__ u64 pk2(float x, float y) {
    u64 d; asm("mov.b64 %0,{%1,%2};" : "=l"(d) : "f"(x), "f"(y)); return d;
}
__device__ __forceinline__ float2 unpk(u64 v) {
    float2 r; asm("mov.b64 {%0,%1},%2;" : "=f"(r.x), "=f"(r.y) : "l"(v)); return r;
}
__device__ __forceinline__ void unpku(u64 v, u32& lo, u32& hi) {
    asm("mov.b64 {%0,%1},%2;" : "=r"(lo), "=r"(hi) : "l"(v));
}

// Scratch
__device__ float g_h0[NB * NS];
__device__ float g_h1[NB * NS];
__device__ float g_h2[NB * NS];
__device__ float g_cs[NB * NS];           // 0.5*|h|^2
__device__ ulonglong2 g_pp0[NB * NS / 2]; // row pairs: {(-h0_e,-h0_o),(-h1_e,-h1_o)}
__device__ ulonglong2 g_pp1[NB * NS / 2]; // row pairs: {(-h2_e,-h2_o),(cs_e, cs_o)}
__device__ int g_maxbits[NB];
__device__ unsigned int g_total[NB];
__device__ unsigned int g_det[NB];
__device__ unsigned int g_vert[NB];
__device__ unsigned int g_done;

#define FUSED_BLOCKS_X 136           // 128 stats + 8 det
#define FUSED_TOTAL (FUSED_BLOCKS_X * NB)

#define XROW 136                     // padded row stride (floats)
#define W1C 776                      // per-part w1t copy stride (768 + 8 bank offset)

// x-tile smem address for (row, float_index k)
__device__ __forceinline__ int xaddr(int row, int k) {
    return row * XROW + ((row >> 2) & 1) * 8 + k;
}

// h = relu(x@w1+b1)@w2+b2.  32 rows/block, 128 threads, smem-staged, 1024 blocks
// so ~7 blocks/SM overlap phase1 (stream) with phase2 (LDS/FMA) across blocks.
__global__ __launch_bounds__(128) void k_embed(
    const float* __restrict__ x, const float* __restrict__ w1,
    const float* __restrict__ b1, const float* __restrict__ w2,
    const float* __restrict__ b2)
{
    if (blockIdx.x == 0) {
        if (threadIdx.x < NB) {
            g_maxbits[threadIdx.x] = 0;
            g_total[threadIdx.x] = 0u;
            g_det[threadIdx.x] = 0u;
            g_vert[threadIdx.x] = 0u;
        }
        if (threadIdx.x == 0) g_done = 0u;
    }

    __shared__ float s_x[32 * XROW + 8];
    __shared__ float s_w1t[4 * W1C];   // 4 bank-offset copies, e-major: [e*128 + k]
    __shared__ float s_b1[6];
    __shared__ float s_b2[3];
    __shared__ float s_w2[18];

    int tid = threadIdx.x;

    // weights: transpose to e-major, 4 copies at 8-float bank offsets
    for (int i = tid; i < NIN * 6; i += 128) {
        int k = i / 6, e = i % 6;
        float v = w1[i];
        s_w1t[0 * W1C + e * NIN + k] = v;
        s_w1t[1 * W1C + e * NIN + k] = v;
        s_w1t[2 * W1C + e * NIN + k] = v;
        s_w1t[3 * W1C + e * NIN + k] = v;
    }
    if (tid < 18) s_w2[tid] = w2[tid];
    if (tid < 6)  s_b1[tid] = b1[tid];
    if (tid < 3)  s_b2[tid] = b2[tid];

    // phase 1: coalesced x tile load (32 rows x 32 float4)
    int row0 = blockIdx.x * 32;
    const float4* xg = (const float4*)(x + (size_t)row0 * NIN);
#pragma unroll
    for (int it = 0; it < 8; it++) {
        int idx = it * 128 + tid;              // 0..1023 float4s
        int row = idx >> 5, q = idx & 31;
        float4 v = xg[idx];
        *(float4*)(s_x + xaddr(row, q * 4)) = v;
    }
    __syncthreads();

    // phase 2: 4 threads/row (warp = 8 rows x 4 parts)
    int row = tid >> 2;        // 0..31
    int part = tid & 3;
    const float* wme = s_w1t + part * W1C;

    float acc[6];
#pragma unroll
    for (int e = 0; e < 6; e++) acc[e] = 0.0f;

#pragma unroll
    for (int j = 0; j < 8; j++) {
        int jj = (j + 2 * part) & 7;          // bank swizzle across parts
        int k = part * 32 + jj * 4;
        float4 v = *(const float4*)(s_x + xaddr(row, k));
#pragma unroll
        for (int e = 0; e < 6; e++) {
            float4 w = *(const float4*)(wme + e * NIN + k);
            acc[e] = fmaf(v.x, w.x, fmaf(v.y, w.y, fmaf(v.z, w.z, fmaf(v.w, w.w, acc[e]))));
        }
    }

    // reduce over 4 parts (butterfly -> all lanes hold full sum)
#pragma unroll
    for (int e = 0; e < 6; e++) {
        acc[e] += __shfl_xor_sync(0xffffffffu, acc[e], 1);
        acc[e] += __shfl_xor_sync(0xffffffffu, acc[e], 2);
        acc[e] = fmaxf(acc[e] + s_b1[e], 0.0f);
    }

    float h0 = s_b2[0], h1 = s_b2[1], h2 = s_b2[2];
#pragma unroll
    for (int e = 0; e < 6; e++) {
        h0 = fmaf(acc[e], s_w2[e * 3 + 0], h0);
        h1 = fmaf(acc[e], s_w2[e * 3 + 1], h1);
        h2 = fmaf(acc[e], s_w2[e * 3 + 2], h2);
    }
    float cs = 0.5f * (h0 * h0 + h1 * h1 + h2 * h2);

    int grow = row0 + row;
    if (part == 0) {
        g_h0[grow] = h0;
        g_h1[grow] = h1;
        g_h2[grow] = h2;
        g_cs[grow] = cs;
    }

    // next row is 4 lanes down (warp rows start even, so pairs stay in-warp)
    float h0n = __shfl_down_sync(0xffffffffu, h0, 4);
    float h1n = __shfl_down_sync(0xffffffffu, h1, 4);
    float h2n = __shfl_down_sync(0xffffffffu, h2, 4);
    float csn = __shfl_down_sync(0xffffffffu, cs, 4);
    if (part == 0 && ((grow & 1) == 0)) {
        ulonglong2 a; a.x = pk2(-h0, -h0n); a.y = pk2(-h1, -h1n);
        ulonglong2 b; b.x = pk2(-h2, -h2n); b.y = pk2(cs, csn);
        g_pp0[grow >> 1] = a;
        g_pp1[grow >> 1] = b;
    }
}

// Pass 1: max of q = cs_r + cs_c - dot = d2/2, brute force, row-pair packed.
// 64-row x 512-col tiles; triangle cover = 80 tiles/batch.
__global__ __launch_bounds__(256, 6) void k_max() {
    int b = blockIdx.y;
    int xx = blockIdx.x;
    int rc, cc;
    if (xx < 32)      { cc = 3; rc = xx; }
    else if (xx < 56) { cc = 2; rc = xx - 32; }
    else if (xx < 72) { cc = 1; rc = xx - 56; }
    else              { cc = 0; rc = xx - 72; }
    int r0 = rc * 64;
    int tid = threadIdx.x;
    const int base = b * NS;
    const int pbase = (b * NS + r0) >> 1;

    __shared__ ulonglong2 sP0[32], sP1[32];
    if (tid < 32) {
        sP0[tid] = g_pp0[pbase + tid];
        sP1[tid] = g_pp1[pbase + tid];
    }
    __syncthreads();

    int cA = cc * 512 + tid;
    float tA0s = g_h0[base + cA], tB0s = g_h0[base + cA + 256];
    float tA1s = g_h1[base + cA], tB1s = g_h1[base + cA + 256];
    float tA2s = g_h2[base + cA], tB2s = g_h2[base + cA + 256];
    float dAs  = g_cs[base + cA], dBs  = g_cs[base + cA + 256];

    u64 tA0 = pk2(tA0s, tA0s), tA1 = pk2(tA1s, tA1s), tA2 = pk2(tA2s, tA2s), dA = pk2(dAs, dAs);
    u64 tB0 = pk2(tB0s, tB0s), tB1 = pk2(tB1s, tB1s), tB2 = pk2(tB2s, tB2s), dB = pk2(dBs, dBs);

    float mAx = 0.0f, mAy = 0.0f, mBx = 0.0f, mBy = 0.0f;
#pragma unroll 8
    for (int j = 0; j < 32; j++) {
        ulonglong2 P0 = sP0[j];
        ulonglong2 P1 = sP1[j];
        u64 qA = f2fma(P0.x, tA0, f2fma(P0.y, tA1, f2fma(P1.x, tA2, f2add(P1.y, dA))));
        u64 qB = f2fma(P0.x, tB0, f2fma(P0.y, tB1, f2fma(P1.x, tB2, f2add(P1.y, dB))));
        float2 fA = unpk(qA), fB = unpk(qB);
        mAx = fmaxf(mAx, fA.x);
        mAy = fmaxf(mAy, fA.y);
        mBx = fmaxf(mBx, fB.x);
        mBy = fmaxf(mBy, fB.y);
    }
    float m = fmaxf(fmaxf(mAx, mAy), fmaxf(mBx, mBy));

    __shared__ float red[256];
    red[tid] = m;
    __syncthreads();
    for (int o = 128; o > 0; o >>= 1) {
        if (tid < o) red[tid] = fmaxf(red[tid], red[tid + o]);
        __syncthreads();
    }
    if (tid == 0) atomicMax(&g_maxbits[b], __float_as_int(2.0f * red[0]));
}

// Fused pass 2: stats (grid.x < 128), det band (grid.x in [128,136)),
// and final output computed by the LAST block via done-counter.
__global__ __launch_bounds__(256, 5) void k_fused(
    const float* __restrict__ thp, const float* __restrict__ w3,
    const float* __restrict__ b3, float* __restrict__ out)
{
    int xx = blockIdx.x;
    int b = blockIdx.y;
    int tid = threadIdx.x;
    const int base = b * NS;

    float th = *thp;
    float sig = 1.0f / (1.0f + expf(-th));
    float hth = 0.5f * sig * sig * __int_as_float(g_maxbits[b]);

    if (xx >= 128) {
        // ---- det band: offsets 1..9, shared-tiled, 256 rows/block ----
        int s0 = (xx - 128) * 256;
        __shared__ float sh0[272], sh1[272], sh2[272], shc[272];
        int nrows = (s0 + 265 <= NS) ? 265 : (NS - s0);
        for (int i = tid; i < nrows; i += 256) {
            sh0[i] = g_h0[base + s0 + i];
            sh1[i] = g_h1[base + s0 + i];
            sh2[i] = g_h2[base + s0 + i];
            shc[i] = g_cs[base + s0 + i];
        }
        __syncthreads();

        unsigned int sum = 0;
        float h0 = sh0[tid], h1 = sh1[tid], h2 = sh2[tid];
        float cs = shc[tid] - hth;
#pragma unroll
        for (int o = 1; o <= 9; o++) {
            int t = tid + o;
            if (s0 + t < NS) {
                float dot = fmaf(h0, sh0[t], fmaf(h1, sh1[t], h2 * sh2[t]));
                sum += (dot > (cs + shc[t])) ? 1u : 0u;
            }
        }
        __shared__ unsigned int redd[256];
        redd[tid] = sum;
        __syncthreads();
        for (int o = 128; o > 0; o >>= 1) {
            if (tid < o) redd[tid] += redd[tid + o];
            __syncthreads();
        }
        if (tid == 0) atomicAdd(&g_det[b], redd[0]);
    } else {
        // ---- stats: 64 rows x 512 cols, rows packed in f32x2 lanes ----
        int cb = xx & 3;
        int rc = xx >> 2;
        int r0 = rc * 64;
        const int pbase = (b * NS + r0) >> 1;

        __shared__ ulonglong2 sP0[32], sP1[32];
        if (tid < 32) {
            sP0[tid] = g_pp0[pbase + tid];
            sP1[tid] = g_pp1[pbase + tid];
        }

        int cA = cb * 512 + tid;
        float tA0s = g_h0[base + cA], tB0s = g_h0[base + cA + 256];
        float tA1s = g_h1[base + cA], tB1s = g_h1[base + cA + 256];
        float tA2s = g_h2[base + cA], tB2s = g_h2[base + cA + 256];
        float dAs = g_cs[base + cA] - hth, dBs = g_cs[base + cA + 256] - hth;

        u64 tA0 = pk2(tA0s, tA0s), tA1 = pk2(tA1s, tA1s), tA2 = pk2(tA2s, tA2s), dA = pk2(dAs, dAs);
        u64 tB0 = pk2(tB0s, tB0s), tB1 = pk2(tB1s, tB1s), tB2 = pk2(tB2s, tB2s), dB = pk2(dBs, dBs);

#define SCBIT(rh0, rh1, rh2, rcs, t0s, t1s, t2s, ds)                              \
    (__float_as_uint(fmaf(-(rh0), (t0s), fmaf(-(rh1), (t1s),                      \
        fmaf(-(rh2), (t2s), (rcs) + (ds))))) >> 31)

        u32 pcA = 0, pcB = 0;
        if (r0 > 0) {
            int r = base + r0 - 1;
            float rh0 = g_h0[r], rh1 = g_h1[r], rh2 = g_h2[r], rcs = g_cs[r];
            pcA = SCBIT(rh0, rh1, rh2, rcs, tA0s, tA1s, tA2s, dAs);
            pcB = SCBIT(rh0, rh1, rh2, rcs, tB0s, tB1s, tB2s, dBs);
        }
        u32 neA = 0, neB = 0;
        if (r0 + 64 < NS) {
            int r = base + r0 + 64;
            float rh0 = g_h0[r], rh1 = g_h1[r], rh2 = g_h2[r], rcs = g_cs[r];
            neA = SCBIT(rh0, rh1, rh2, rcs, tA0s, tA1s, tA2s, dAs);
            neB = SCBIT(rh0, rh1, rh2, rcs, tB0s, tB1s, tB2s, dBs);
        }
        __syncthreads();

        u32 utot = 0, uvert = 0;
        u32 pendA = 0, pendB = 0;

#define PROCESS(pd, pc, nf)                                                      \
    {                                                                            \
        u32 prevw = (pd >> 1) | (pc << 31);                                      \
        u32 nextw = (pd << 1) | (nf);                                            \
        uvert += __popc(pd & ~prevw & nextw);                                    \
        utot += __popc(pd);                                                      \
        pc = pd & 1u;                                                            \
    }

#pragma unroll
        for (int wi = 0; wi < 2; wi++) {
            u32 wA = 0, wB = 0;
#pragma unroll
            for (int jj = 0; jj < 16; jj++) {
                int j = wi * 16 + jj;
                ulonglong2 P0 = sP0[j];
                ulonglong2 P1 = sP1[j];
                u64 qA = f2fma(P0.x, tA0, f2fma(P0.y, tA1, f2fma(P1.x, tA2, f2add(P1.y, dA))));
                u64 qB = f2fma(P0.x, tB0, f2fma(P0.y, tB1, f2fma(P1.x, tB2, f2add(P1.y, dB))));
                u32 lA, hA, lB, hB;
                unpku(qA, lA, hA);
                unpku(qB, lB, hB);
                wA = __funnelshift_l(lA, wA, 1);
                wA = __funnelshift_l(hA, wA, 1);
                wB = __funnelshift_l(lB, wB, 1);
                wB = __funnelshift_l(hB, wB, 1);
            }
            if (wi > 0) {
                u32 nfA = wA >> 31, nfB = wB >> 31;
                PROCESS(pendA, pcA, nfA);
                PROCESS(pendB, pcB, nfB);
            }
            pendA = wA;
            pendB = wB;
        }
        PROCESS(pendA, pcA, neA);
        PROCESS(pendB, pcB, neB);

#undef PROCESS
#undef SCBIT

        __shared__ unsigned int rt[256], rv[256];
        rt[tid] = utot;
        rv[tid] = uvert;
        __syncthreads();
        for (int o = 128; o > 0; o >>= 1) {
            if (tid < o) { rt[tid] += rt[tid + o]; rv[tid] += rv[tid + o]; }
            __syncthreads();
        }
        if (tid == 0) {
            atomicAdd(&g_total[b], rt[0]);
            atomicAdd(&g_vert[b], rv[0]);
        }
    }

    // ---- last-block final ----
    __threadfence();
    __shared__ unsigned int s_last;
    if (tid == 0) s_last = (atomicAdd(&g_done, 1u) == FUSED_TOTAL - 1u) ? 1u : 0u;
    __syncthreads();
    if (s_last) {
        for (int k = tid; k < NB * 64; k += 256) {
            int bb = k >> 6;
            int j = k & 63;
            float total = (float)g_total[bb];
            float denom = total + 1e-6f;
            float rr = total * (1.0f / ((float)NS * (float)NS));
            float det = (float)g_det[bb] / denom;
            float lam = (float)g_vert[bb] / denom;
            float entr = -total * logf(1.0f + 1e-6f);
            float v = fmaf(rr, w3[j],
                      fmaf(det, w3[64 + j],
                      fmaf(lam, w3[128 + j],
                      fmaf(entr, w3[192 + j], b3[j]))));
            out[k] = fmaxf(v, 0.0f);
        }
    }
}

extern "C" void kernel_launch(void* const* d_in, const int* in_sizes, int n_in,
                              void* d_out, int out_size) {
    const float* x  = (const float*)d_in[0];
    const float* th = (const float*)d_in[1];
    const float* w1 = (const float*)d_in[2];
    const float* b1 = (const float*)d_in[3];
    const float* w2 = (const float*)d_in[4];
    const float* b2 = (const float*)d_in[5];
    const float* w3 = (const float*)d_in[6];
    const float* b3 = (const float*)d_in[7];
    float* out = (float*)d_out;

    k_embed<<<1024, 128>>>(x, w1, b1, w2, b2);
    k_max<<<dim3(80, NB), 256>>>();
    k_fused<<<dim3(FUSED_BLOCKS_X, NB), 256>>>(th, w3, b3, out);
}

// round 13
// speedup vs baseline: 1.0475x; 1.0475x over previous
#include <cuda_runtime.h>
#include <math.h>

#define NB 16
#define NS 2048
#define NIN 128

typedef unsigned long long u64;
typedef unsigned int u32;

__device__ __forceinline__ u64 f2fma(u64 a, u64 b, u64 c) {
    u64 d; asm("fma.rn.f32x2 %0,%1,%2,%3;" : "=l"(d) : "l"(a), "l"(b), "l"(c)); return d;
}
__device__ __forceinline__ u64 f2mul(u64 a, u64 b) {
    u64 d; asm("mul.rn.f32x2 %0,%1,%2;" : "=l"(d) : "l"(a), "l"(b)); return d;
}
__device__ __forceinline__ u64 f2add(u64 a, u64 b) {
    u64 d; asm("add.rn.f32x2 %0,%1,%2;" : "=l"(d) : "l"(a), "l"(b)); return d;
}
__device__ __forceinline__ u64 pk2(float x, float y) {
    u64 d; asm("mov.b64 %0,{%1,%2};" : "=l"(d) : "f"(x), "f"(y)); return d;
}
__device__ __forceinline__ float2 unpk(u64 v) {
    float2 r; asm("mov.b64 {%0,%1},%2;" : "=f"(r.x), "=f"(r.y) : "l"(v)); return r;
}
__device__ __forceinline__ void unpku(u64 v, u32& lo, u32& hi) {
    asm("mov.b64 {%0,%1},%2;" : "=r"(lo), "=r"(hi) : "l"(v));
}

// Scratch
__device__ float g_h0[NB * NS];
__device__ float g_h1[NB * NS];
__device__ float g_h2[NB * NS];
__device__ float g_cs[NB * NS];           // 0.5*|h|^2
__device__ ulonglong2 g_pp0[NB * NS / 2]; // row pairs: {(-h0_e,-h0_o),(-h1_e,-h1_o)}
__device__ ulonglong2 g_pp1[NB * NS / 2]; // row pairs: {(-h2_e,-h2_o),(cs_e, cs_o)}
__device__ int g_maxbits[NB];
__device__ unsigned int g_total[NB];
__device__ unsigned int g_det[NB];
__device__ unsigned int g_vert[NB];
__device__ unsigned int g_done;

#define FUSED_BLOCKS_X 136           // 128 stats + 8 det
#define FUSED_TOTAL (FUSED_BLOCKS_X * NB)

// h = relu(x@w1+b1)@w2+b2.
// 16 lanes per row; weights register-resident (24 packed u64/lane); 4-round
// shuffle reduction; no shared memory in the hot loop.
// 512 blocks x 256 threads = 4096 warps x 4 row-pairs each = 32768 rows.
__global__ __launch_bounds__(256) void k_embed(
    const float* __restrict__ x, const float* __restrict__ w1,
    const float* __restrict__ b1, const float* __restrict__ w2,
    const float* __restrict__ b2)
{
    int tid = threadIdx.x;
    if (blockIdx.x == 0) {
        if (tid < NB) {
            g_maxbits[tid] = 0;
            g_total[tid] = 0u;
            g_det[tid] = 0u;
            g_vert[tid] = 0u;
        }
        if (tid == 0) g_done = 0u;
    }

    __shared__ float s_c[27];   // [0:6) b1, [6:24) w2, [24:27) b2
    if (tid < 6)  s_c[tid] = b1[tid];
    if (tid < 18) s_c[6 + tid] = w2[tid];
    if (tid < 3)  s_c[24 + tid] = b2[tid];

    int lane = tid & 31;
    int warp = (blockIdx.x * 256 + tid) >> 5;   // 0..4095
    int half = lane >> 4;                       // which row of the pair
    int kl = lane & 15;                         // k-slice index

    // Load this lane's 48 weights (k in {4kl..4kl+3} U {64+4kl..64+4kl+3}),
    // pack into u64 pairs over adjacent k: wA/wB[kk*6+e] = (w[2kk][e], w[2kk+1][e])
    float ca[24], cb[24];
    {
        const float4* wga = (const float4*)(w1 + kl * 24);
        const float4* wgb = (const float4*)(w1 + 384 + kl * 24);
#pragma unroll
        for (int i = 0; i < 6; i++) {
            *(float4*)(ca + 4 * i) = wga[i];
            *(float4*)(cb + 4 * i) = wgb[i];
        }
    }
    u64 wA[12], wB[12];
#pragma unroll
    for (int kk = 0; kk < 2; kk++)
#pragma unroll
        for (int e = 0; e < 6; e++) {
            wA[kk * 6 + e] = pk2(ca[12 * kk + e], ca[12 * kk + 6 + e]);
            wB[kk * 6 + e] = pk2(cb[12 * kk + e], cb[12 * kk + 6 + e]);
        }
    __syncthreads();

#pragma unroll
    for (int it = 0; it < 4; it++) {
        int p = warp * 4 + it;           // row-pair index 0..16383
        int r = 2 * p + half;            // this half's row

        const float4* xr = (const float4*)(x + (size_t)r * NIN);
        float4 xa = xr[kl];
        float4 xb = xr[16 + kl];
        u64 p0 = pk2(xa.x, xa.y), p1 = pk2(xa.z, xa.w);
        u64 p2 = pk2(xb.x, xb.y), p3 = pk2(xb.z, xb.w);

        float s[6];
#pragma unroll
        for (int e = 0; e < 6; e++) {
            u64 acc = f2fma(p0, wA[e],
                      f2fma(p1, wA[6 + e],
                      f2fma(p2, wB[e],
                      f2mul(p3, wB[6 + e]))));
            float2 f = unpk(acc);
            s[e] = f.x + f.y;
        }

        // reduce over the 16 lanes of this half (xor 1,2,4,8 stays in-half)
#pragma unroll
        for (int o = 1; o <= 8; o <<= 1) {
#pragma unroll
            for (int e = 0; e < 6; e++)
                s[e] += __shfl_xor_sync(0xffffffffu, s[e], o);
        }

        float h0 = s_c[24], h1 = s_c[25], h2 = s_c[26];
#pragma unroll
        for (int e = 0; e < 6; e++) {
            float t = fmaxf(s[e] + s_c[e], 0.0f);
            h0 = fmaf(t, s_c[6 + e * 3 + 0], h0);
            h1 = fmaf(t, s_c[6 + e * 3 + 1], h1);
            h2 = fmaf(t, s_c[6 + e * 3 + 2], h2);
        }
        float cs = 0.5f * (h0 * h0 + h1 * h1 + h2 * h2);

        if (kl == 0) {                   // lanes 0 (row 2p) and 16 (row 2p+1)
            g_h0[r] = h0;
            g_h1[r] = h1;
            g_h2[r] = h2;
            g_cs[r] = cs;
        }

        float h0o = __shfl_down_sync(0xffffffffu, h0, 16);
        float h1o = __shfl_down_sync(0xffffffffu, h1, 16);
        float h2o = __shfl_down_sync(0xffffffffu, h2, 16);
        float cso = __shfl_down_sync(0xffffffffu, cs, 16);
        if (lane == 0) {
            ulonglong2 a; a.x = pk2(-h0, -h0o); a.y = pk2(-h1, -h1o);
            ulonglong2 b; b.x = pk2(-h2, -h2o); b.y = pk2(cs, cso);
            g_pp0[p] = a;
            g_pp1[p] = b;
        }
    }
}

// Pass 1: max of q = cs_r + cs_c - dot = d2/2, brute force, row-pair packed.
// 64-row x 512-col tiles; triangle cover = 80 tiles/batch.
__global__ __launch_bounds__(256, 6) void k_max() {
    int b = blockIdx.y;
    int xx = blockIdx.x;
    int rc, cc;
    if (xx < 32)      { cc = 3; rc = xx; }
    else if (xx < 56) { cc = 2; rc = xx - 32; }
    else if (xx < 72) { cc = 1; rc = xx - 56; }
    else              { cc = 0; rc = xx - 72; }
    int r0 = rc * 64;
    int tid = threadIdx.x;
    const int base = b * NS;
    const int pbase = (b * NS + r0) >> 1;

    __shared__ ulonglong2 sP0[32], sP1[32];
    if (tid < 32) {
        sP0[tid] = g_pp0[pbase + tid];
        sP1[tid] = g_pp1[pbase + tid];
    }
    __syncthreads();

    int cA = cc * 512 + tid;
    float tA0s = g_h0[base + cA], tB0s = g_h0[base + cA + 256];
    float tA1s = g_h1[base + cA], tB1s = g_h1[base + cA + 256];
    float tA2s = g_h2[base + cA], tB2s = g_h2[base + cA + 256];
    float dAs  = g_cs[base + cA], dBs  = g_cs[base + cA + 256];

    u64 tA0 = pk2(tA0s, tA0s), tA1 = pk2(tA1s, tA1s), tA2 = pk2(tA2s, tA2s), dA = pk2(dAs, dAs);
    u64 tB0 = pk2(tB0s, tB0s), tB1 = pk2(tB1s, tB1s), tB2 = pk2(tB2s, tB2s), dB = pk2(dBs, dBs);

    float mAx = 0.0f, mAy = 0.0f, mBx = 0.0f, mBy = 0.0f;
#pragma unroll 8
    for (int j = 0; j < 32; j++) {
        ulonglong2 P0 = sP0[j];
        ulonglong2 P1 = sP1[j];
        u64 qA = f2fma(P0.x, tA0, f2fma(P0.y, tA1, f2fma(P1.x, tA2, f2add(P1.y, dA))));
        u64 qB = f2fma(P0.x, tB0, f2fma(P0.y, tB1, f2fma(P1.x, tB2, f2add(P1.y, dB))));
        float2 fA = unpk(qA), fB = unpk(qB);
        mAx = fmaxf(mAx, fA.x);
        mAy = fmaxf(mAy, fA.y);
        mBx = fmaxf(mBx, fB.x);
        mBy = fmaxf(mBy, fB.y);
    }
    float m = fmaxf(fmaxf(mAx, mAy), fmaxf(mBx, mBy));

    __shared__ float red[256];
    red[tid] = m;
    __syncthreads();
    for (int o = 128; o > 0; o >>= 1) {
        if (tid < o) red[tid] = fmaxf(red[tid], red[tid + o]);
        __syncthreads();
    }
    if (tid == 0) atomicMax(&g_maxbits[b], __float_as_int(2.0f * red[0]));
}

// Fused pass 2: stats (grid.x < 128), det band (grid.x in [128,136)),
// and final output computed by the LAST block via done-counter.
__global__ __launch_bounds__(256, 5) void k_fused(
    const float* __restrict__ thp, const float* __restrict__ w3,
    const float* __restrict__ b3, float* __restrict__ out)
{
    int xx = blockIdx.x;
    int b = blockIdx.y;
    int tid = threadIdx.x;
    const int base = b * NS;

    float th = *thp;
    float sig = 1.0f / (1.0f + expf(-th));
    float hth = 0.5f * sig * sig * __int_as_float(g_maxbits[b]);

    if (xx >= 128) {
        // ---- det band: offsets 1..9, shared-tiled, 256 rows/block ----
        int s0 = (xx - 128) * 256;
        __shared__ float sh0[272], sh1[272], sh2[272], shc[272];
        int nrows = (s0 + 265 <= NS) ? 265 : (NS - s0);
        for (int i = tid; i < nrows; i += 256) {
            sh0[i] = g_h0[base + s0 + i];
            sh1[i] = g_h1[base + s0 + i];
            sh2[i] = g_h2[base + s0 + i];
            shc[i] = g_cs[base + s0 + i];
        }
        __syncthreads();

        unsigned int sum = 0;
        float h0 = sh0[tid], h1 = sh1[tid], h2 = sh2[tid];
        float cs = shc[tid] - hth;
#pragma unroll
        for (int o = 1; o <= 9; o++) {
            int t = tid + o;
            if (s0 + t < NS) {
                float dot = fmaf(h0, sh0[t], fmaf(h1, sh1[t], h2 * sh2[t]));
                sum += (dot > (cs + shc[t])) ? 1u : 0u;
            }
        }
        __shared__ unsigned int redd[256];
        redd[tid] = sum;
        __syncthreads();
        for (int o = 128; o > 0; o >>= 1) {
            if (tid < o) redd[tid] += redd[tid + o];
            __syncthreads();
        }
        if (tid == 0) atomicAdd(&g_det[b], redd[0]);
    } else {
        // ---- stats: 64 rows x 512 cols, rows packed in f32x2 lanes ----
        int cb = xx & 3;
        int rc = xx >> 2;
        int r0 = rc * 64;
        const int pbase = (b * NS + r0) >> 1;

        __shared__ ulonglong2 sP0[32], sP1[32];
        if (tid < 32) {
            sP0[tid] = g_pp0[pbase + tid];
            sP1[tid] = g_pp1[pbase + tid];
        }

        int cA = cb * 512 + tid;
        float tA0s = g_h0[base + cA], tB0s = g_h0[base + cA + 256];
        float tA1s = g_h1[base + cA], tB1s = g_h1[base + cA + 256];
        float tA2s = g_h2[base + cA], tB2s = g_h2[base + cA + 256];
        float dAs = g_cs[base + cA] - hth, dBs = g_cs[base + cA + 256] - hth;

        u64 tA0 = pk2(tA0s, tA0s), tA1 = pk2(tA1s, tA1s), tA2 = pk2(tA2s, tA2s), dA = pk2(dAs, dAs);
        u64 tB0 = pk2(tB0s, tB0s), tB1 = pk2(tB1s, tB1s), tB2 = pk2(tB2s, tB2s), dB = pk2(dBs, dBs);

#define SCBIT(rh0, rh1, rh2, rcs, t0s, t1s, t2s, ds)                              \
    (__float_as_uint(fmaf(-(rh0), (t0s), fmaf(-(rh1), (t1s),                      \
        fmaf(-(rh2), (t2s), (rcs) + (ds))))) >> 31)

        u32 pcA = 0, pcB = 0;
        if (r0 > 0) {
            int r = base + r0 - 1;
            float rh0 = g_h0[r], rh1 = g_h1[r], rh2 = g_h2[r], rcs = g_cs[r];
            pcA = SCBIT(rh0, rh1, rh2, rcs, tA0s, tA1s, tA2s, dAs);
            pcB = SCBIT(rh0, rh1, rh2, rcs, tB0s, tB1s, tB2s, dBs);
        }
        u32 neA = 0, neB = 0;
        if (r0 + 64 < NS) {
            int r = base + r0 + 64;
            float rh0 = g_h0[r], rh1 = g_h1[r], rh2 = g_h2[r], rcs = g_cs[r];
            neA = SCBIT(rh0, rh1, rh2, rcs, tA0s, tA1s, tA2s, dAs);
            neB = SCBIT(rh0, rh1, rh2, rcs, tB0s, tB1s, tB2s, dBs);
        }
        __syncthreads();

        u32 utot = 0, uvert = 0;
        u32 pendA = 0, pendB = 0;

#define PROCESS(pd, pc, nf)                                                      \
    {                                                                            \
        u32 prevw = (pd >> 1) | (pc << 31);                                      \
        u32 nextw = (pd << 1) | (nf);                                            \
        uvert += __popc(pd & ~prevw & nextw);                                    \
        utot += __popc(pd);                                                      \
        pc = pd & 1u;                                                            \
    }

#pragma unroll
        for (int wi = 0; wi < 2; wi++) {
            u32 wA = 0, wB = 0;
#pragma unroll
            for (int jj = 0; jj < 16; jj++) {
                int j = wi * 16 + jj;
                ulonglong2 P0 = sP0[j];
                ulonglong2 P1 = sP1[j];
                u64 qA = f2fma(P0.x, tA0, f2fma(P0.y, tA1, f2fma(P1.x, tA2, f2add(P1.y, dA))));
                u64 qB = f2fma(P0.x, tB0, f2fma(P0.y, tB1, f2fma(P1.x, tB2, f2add(P1.y, dB))));
                u32 lA, hA, lB, hB;
                unpku(qA, lA, hA);
                unpku(qB, lB, hB);
                wA = __funnelshift_l(lA, wA, 1);
                wA = __funnelshift_l(hA, wA, 1);
                wB = __funnelshift_l(lB, wB, 1);
                wB = __funnelshift_l(hB, wB, 1);
            }
            if (wi > 0) {
                u32 nfA = wA >> 31, nfB = wB >> 31;
                PROCESS(pendA, pcA, nfA);
                PROCESS(pendB, pcB, nfB);
            }
            pendA = wA;
            pendB = wB;
        }
        PROCESS(pendA, pcA, neA);
        PROCESS(pendB, pcB, neB);

#undef PROCESS
#undef SCBIT

        __shared__ unsigned int rt[256], rv[256];
        rt[tid] = utot;
        rv[tid] = uvert;
        __syncthreads();
        for (int o = 128; o > 0; o >>= 1) {
            if (tid < o) { rt[tid] += rt[tid + o]; rv[tid] += rv[tid + o]; }
            __syncthreads();
        }
        if (tid == 0) {
            atomicAdd(&g_total[b], rt[0]);
            atomicAdd(&g_vert[b], rv[0]);
        }
    }

    // ---- last-block final ----
    __threadfence();
    __shared__ unsigned int s_last;
    if (tid == 0) s_last = (atomicAdd(&g_done, 1u) == FUSED_TOTAL - 1u) ? 1u : 0u;
    __syncthreads();
    if (s_last) {
        for (int k = tid; k < NB * 64; k += 256) {
            int bb = k >> 6;
            int j = k & 63;
            float total = (float)g_total[bb];
            float denom = total + 1e-6f;
            float rr = total * (1.0f / ((float)NS * (float)NS));
            float det = (float)g_det[bb] / denom;
            float lam = (float)g_vert[bb] / denom;
            float entr = -total * logf(1.0f + 1e-6f);
            float v = fmaf(rr, w3[j],
                      fmaf(det, w3[64 + j],
                      fmaf(lam, w3[128 + j],
                      fmaf(entr, w3[192 + j], b3[j]))));
            out[k] = fmaxf(v, 0.0f);
        }
    }
}

extern "C" void kernel_launch(void* const* d_in, const int* in_sizes, int n_in,
                              void* d_out, int out_size) {
    const float* x  = (const float*)d_in[0];
    const float* th = (const float*)d_in[1];
    const float* w1 = (const float*)d_in[2];
    const float* b1 = (const float*)d_in[3];
    const float* w2 = (const float*)d_in[4];
    const float* b2 = (const float*)d_in[5];
    const float* w3 = (const float*)d_in[6];
    const float* b3 = (const float*)d_in[7];
    float* out = (float*)d_out;

    k_embed<<<512, 256>>>(x, w1, b1, w2, b2);
    k_max<<<dim3(80, NB), 256>>>();
    k_fused<<<dim3(FUSED_BLOCKS_X, NB), 256>>>(th, w3, b3, out);
}

// round 14
// speedup vs baseline: 1.1058x; 1.0556x over previous
#include <cuda_runtime.h>
#include <math.h>

#define NB 16
#define NS 2048
#define NIN 128

typedef unsigned long long u64;
typedef unsigned int u32;

__device__ __forceinline__ u64 f2fma(u64 a, u64 b, u64 c) {
    u64 d; asm("fma.rn.f32x2 %0,%1,%2,%3;" : "=l"(d) : "l"(a), "l"(b), "l"(c)); return d;
}
__device__ __forceinline__ u64 f2mul(u64 a, u64 b) {
    u64 d; asm("mul.rn.f32x2 %0,%1,%2;" : "=l"(d) : "l"(a), "l"(b)); return d;
}
__device__ __forceinline__ u64 f2add(u64 a, u64 b) {
    u64 d; asm("add.rn.f32x2 %0,%1,%2;" : "=l"(d) : "l"(a), "l"(b)); return d;
}
__device__ __forceinline__ u64 pk2(float x, float y) {
    u64 d; asm("mov.b64 %0,{%1,%2};" : "=l"(d) : "f"(x), "f"(y)); return d;
}
__device__ __forceinline__ float2 unpk(u64 v) {
    float2 r; asm("mov.b64 {%0,%1},%2;" : "=f"(r.x), "=f"(r.y) : "l"(v)); return r;
}
__device__ __forceinline__ void unpku(u64 v, u32& lo, u32& hi) {
    asm("mov.b64 {%0,%1},%2;" : "=r"(lo), "=r"(hi) : "l"(v));
}

// Scratch
__device__ float g_h0[NB * NS];
__device__ float g_h1[NB * NS];
__device__ float g_h2[NB * NS];
__device__ float g_cs[NB * NS];           // 0.5*|h|^2
__device__ ulonglong2 g_pp0[NB * NS / 2]; // row pairs: {(-h0_e,-h0_o),(-h1_e,-h1_o)}
__device__ ulonglong2 g_pp1[NB * NS / 2]; // row pairs: {(-h2_e,-h2_o),(cs_e, cs_o)}
__device__ int g_maxbits[NB];
__device__ unsigned int g_total[NB];
__device__ unsigned int g_det[NB];
__device__ unsigned int g_vert[NB];
__device__ unsigned int g_done;

#define FUSED_BLOCKS_X 136           // 128 stats + 8 det
#define FUSED_TOTAL (FUSED_BLOCKS_X * NB)

// h = relu(x@w1+b1)@w2+b2.
// 16 lanes per row; weights register-resident; shuffle reduction; outputs staged
// in smem and flushed coalesced. 512 blocks x 256 threads; 64 rows/block.
__global__ __launch_bounds__(256) void k_embed(
    const float* __restrict__ x, const float* __restrict__ w1,
    const float* __restrict__ b1, const float* __restrict__ w2,
    const float* __restrict__ b2)
{
    int tid = threadIdx.x;
    if (blockIdx.x == 0) {
        if (tid < NB) {
            g_maxbits[tid] = 0;
            g_total[tid] = 0u;
            g_det[tid] = 0u;
            g_vert[tid] = 0u;
        }
        if (tid == 0) g_done = 0u;
    }

    __shared__ float s_c[27];   // [0:6) b1, [6:24) w2, [24:27) b2
    __shared__ float sh0[64], sh1[64], sh2[64], shc[64];
    if (tid < 6)  s_c[tid] = b1[tid];
    if (tid < 18) s_c[6 + tid] = w2[tid];
    if (tid < 3)  s_c[24 + tid] = b2[tid];

    int lane = tid & 31;
    int wl = tid >> 5;                          // warp in block, 0..7
    int half = lane >> 4;                       // which row of the pair
    int kl = lane & 15;                         // k-slice index
    int row0 = blockIdx.x * 64;

    // Load this lane's 48 weights, pack into u64 pairs over adjacent k.
    float ca[24], cb[24];
    {
        const float4* wga = (const float4*)(w1 + kl * 24);
        const float4* wgb = (const float4*)(w1 + 384 + kl * 24);
#pragma unroll
        for (int i = 0; i < 6; i++) {
            *(float4*)(ca + 4 * i) = wga[i];
            *(float4*)(cb + 4 * i) = wgb[i];
        }
    }
    u64 wA[12], wB[12];
#pragma unroll
    for (int kk = 0; kk < 2; kk++)
#pragma unroll
        for (int e = 0; e < 6; e++) {
            wA[kk * 6 + e] = pk2(ca[12 * kk + e], ca[12 * kk + 6 + e]);
            wB[kk * 6 + e] = pk2(cb[12 * kk + e], cb[12 * kk + 6 + e]);
        }
    __syncthreads();

#pragma unroll
    for (int it = 0; it < 4; it++) {
        int pl = wl * 4 + it;            // local pair 0..31
        int rl = 2 * pl + half;          // local row 0..63
        int r = row0 + rl;

        const float4* xr = (const float4*)(x + (size_t)r * NIN);
        float4 xa = xr[kl];
        float4 xb = xr[16 + kl];
        u64 p0 = pk2(xa.x, xa.y), p1 = pk2(xa.z, xa.w);
        u64 p2 = pk2(xb.x, xb.y), p3 = pk2(xb.z, xb.w);

        float s[6];
#pragma unroll
        for (int e = 0; e < 6; e++) {
            u64 acc = f2fma(p0, wA[e],
                      f2fma(p1, wA[6 + e],
                      f2fma(p2, wB[e],
                      f2mul(p3, wB[6 + e]))));
            float2 f = unpk(acc);
            s[e] = f.x + f.y;
        }

#pragma unroll
        for (int o = 1; o <= 8; o <<= 1) {
#pragma unroll
            for (int e = 0; e < 6; e++)
                s[e] += __shfl_xor_sync(0xffffffffu, s[e], o);
        }

        float h0 = s_c[24], h1 = s_c[25], h2 = s_c[26];
#pragma unroll
        for (int e = 0; e < 6; e++) {
            float t = fmaxf(s[e] + s_c[e], 0.0f);
            h0 = fmaf(t, s_c[6 + e * 3 + 0], h0);
            h1 = fmaf(t, s_c[6 + e * 3 + 1], h1);
            h2 = fmaf(t, s_c[6 + e * 3 + 2], h2);
        }
        float cs = 0.5f * (h0 * h0 + h1 * h1 + h2 * h2);

        if (kl == 0) {                   // lanes 0 (even row) and 16 (odd row)
            sh0[rl] = h0;
            sh1[rl] = h1;
            sh2[rl] = h2;
            shc[rl] = cs;
        }
    }
    __syncthreads();

    // coalesced flush: 4 arrays x 64 rows
    {
        int arr = tid >> 6, idx = tid & 63;
        float v = (arr == 0) ? sh0[idx] : (arr == 1) ? sh1[idx]
                : (arr == 2) ? sh2[idx] : shc[idx];
        float* dst = (arr == 0) ? g_h0 : (arr == 1) ? g_h1
                   : (arr == 2) ? g_h2 : g_cs;
        dst[row0 + idx] = v;
    }
    // pp pairs: 32 per block, built from smem
    if (tid < 32) {
        int pb = (row0 >> 1) + tid;
        float e0 = sh0[2 * tid], o0 = sh0[2 * tid + 1];
        float e1 = sh1[2 * tid], o1 = sh1[2 * tid + 1];
        float e2 = sh2[2 * tid], o2 = sh2[2 * tid + 1];
        float ec = shc[2 * tid], oc = shc[2 * tid + 1];
        ulonglong2 a; a.x = pk2(-e0, -o0); a.y = pk2(-e1, -o1);
        ulonglong2 b; b.x = pk2(-e2, -o2); b.y = pk2(ec, oc);
        g_pp0[pb] = a;
        g_pp1[pb] = b;
    }
}

// Pass 1: max of q = cs_r + cs_c - dot = d2/2, brute force, row-pair packed.
// 64-row x 512-col tiles; triangle cover = 80 tiles/batch.
__global__ __launch_bounds__(256, 6) void k_max() {
    int b = blockIdx.y;
    int xx = blockIdx.x;
    int rc, cc;
    if (xx < 32)      { cc = 3; rc = xx; }
    else if (xx < 56) { cc = 2; rc = xx - 32; }
    else if (xx < 72) { cc = 1; rc = xx - 56; }
    else              { cc = 0; rc = xx - 72; }
    int r0 = rc * 64;
    int tid = threadIdx.x;
    const int base = b * NS;
    const int pbase = (b * NS + r0) >> 1;

    __shared__ ulonglong2 sP0[32], sP1[32];
    if (tid < 32) {
        sP0[tid] = g_pp0[pbase + tid];
        sP1[tid] = g_pp1[pbase + tid];
    }
    __syncthreads();

    int cA = cc * 512 + tid;
    float tA0s = g_h0[base + cA], tB0s = g_h0[base + cA + 256];
    float tA1s = g_h1[base + cA], tB1s = g_h1[base + cA + 256];
    float tA2s = g_h2[base + cA], tB2s = g_h2[base + cA + 256];
    float dAs  = g_cs[base + cA], dBs  = g_cs[base + cA + 256];

    u64 tA0 = pk2(tA0s, tA0s), tA1 = pk2(tA1s, tA1s), tA2 = pk2(tA2s, tA2s), dA = pk2(dAs, dAs);
    u64 tB0 = pk2(tB0s, tB0s), tB1 = pk2(tB1s, tB1s), tB2 = pk2(tB2s, tB2s), dB = pk2(dBs, dBs);

    float mAx = 0.0f, mAy = 0.0f, mBx = 0.0f, mBy = 0.0f;
#pragma unroll 8
    for (int j = 0; j < 32; j++) {
        ulonglong2 P0 = sP0[j];
        ulonglong2 P1 = sP1[j];
        u64 qA = f2fma(P0.x, tA0, f2fma(P0.y, tA1, f2fma(P1.x, tA2, f2add(P1.y, dA))));
        u64 qB = f2fma(P0.x, tB0, f2fma(P0.y, tB1, f2fma(P1.x, tB2, f2add(P1.y, dB))));
        float2 fA = unpk(qA), fB = unpk(qB);
        mAx = fmaxf(mAx, fA.x);
        mAy = fmaxf(mAy, fA.y);
        mBx = fmaxf(mBx, fB.x);
        mBy = fmaxf(mBy, fB.y);
    }
    float m = fmaxf(fmaxf(mAx, mAy), fmaxf(mBx, mBy));

    __shared__ float red[256];
    red[tid] = m;
    __syncthreads();
    for (int o = 128; o > 0; o >>= 1) {
        if (tid < o) red[tid] = fmaxf(red[tid], red[tid + o]);
        __syncthreads();
    }
    if (tid == 0) atomicMax(&g_maxbits[b], __float_as_int(2.0f * red[0]));
}

// Fused pass 2: stats (grid.x < 128), det band (grid.x in [128,136)),
// and final output computed by the LAST block via done-counter.
// Stats: even/odd bit-plane words (E,O) per column, single 32-iteration pass.
__global__ __launch_bounds__(256, 6) void k_fused(
    const float* __restrict__ thp, const float* __restrict__ w3,
    const float* __restrict__ b3, float* __restrict__ out)
{
    int xx = blockIdx.x;
    int b = blockIdx.y;
    int tid = threadIdx.x;
    const int base = b * NS;

    float th = *thp;
    float sig = 1.0f / (1.0f + expf(-th));
    float hth = 0.5f * sig * sig * __int_as_float(g_maxbits[b]);

    if (xx >= 128) {
        // ---- det band: offsets 1..9, shared-tiled, 256 rows/block ----
        int s0 = (xx - 128) * 256;
        __shared__ float sh0[272], sh1[272], sh2[272], shc[272];
        int nrows = (s0 + 265 <= NS) ? 265 : (NS - s0);
        for (int i = tid; i < nrows; i += 256) {
            sh0[i] = g_h0[base + s0 + i];
            sh1[i] = g_h1[base + s0 + i];
            sh2[i] = g_h2[base + s0 + i];
            shc[i] = g_cs[base + s0 + i];
        }
        __syncthreads();

        unsigned int sum = 0;
        float h0 = sh0[tid], h1 = sh1[tid], h2 = sh2[tid];
        float cs = shc[tid] - hth;
#pragma unroll
        for (int o = 1; o <= 9; o++) {
            int t = tid + o;
            if (s0 + t < NS) {
                float dot = fmaf(h0, sh0[t], fmaf(h1, sh1[t], h2 * sh2[t]));
                sum += (dot > (cs + shc[t])) ? 1u : 0u;
            }
        }
        __shared__ unsigned int redd[256];
        redd[tid] = sum;
        __syncthreads();
        for (int o = 128; o > 0; o >>= 1) {
            if (tid < o) redd[tid] += redd[tid + o];
            __syncthreads();
        }
        if (tid == 0) atomicAdd(&g_det[b], redd[0]);
    } else {
        // ---- stats: 64 rows x 512 cols; E/O bit planes per column ----
        int cb = xx & 3;
        int rc = xx >> 2;
        int r0 = rc * 64;
        const int pbase = (b * NS + r0) >> 1;

        __shared__ ulonglong2 sP0[32], sP1[32];
        if (tid < 32) {
            sP0[tid] = g_pp0[pbase + tid];
            sP1[tid] = g_pp1[pbase + tid];
        }

        int cA = cb * 512 + tid;
        float tA0s = g_h0[base + cA], tB0s = g_h0[base + cA + 256];
        float tA1s = g_h1[base + cA], tB1s = g_h1[base + cA + 256];
        float tA2s = g_h2[base + cA], tB2s = g_h2[base + cA + 256];
        float dAs = g_cs[base + cA] - hth, dBs = g_cs[base + cA + 256] - hth;

        u64 tA0 = pk2(tA0s, tA0s), tA1 = pk2(tA1s, tA1s), tA2 = pk2(tA2s, tA2s), dA = pk2(dAs, dAs);
        u64 tB0 = pk2(tB0s, tB0s), tB1 = pk2(tB1s, tB1s), tB2 = pk2(tB2s, tB2s), dB = pk2(dBs, dBs);

#define SCBIT(rh0, rh1, rh2, rcs, t0s, t1s, t2s, ds)                              \
    (__float_as_uint(fmaf(-(rh0), (t0s), fmaf(-(rh1), (t1s),                      \
        fmaf(-(rh2), (t2s), (rcs) + (ds))))) >> 31)

        u32 pcA = 0, pcB = 0;    // R[r0-1]
        if (r0 > 0) {
            int r = base + r0 - 1;
            float rh0 = g_h0[r], rh1 = g_h1[r], rh2 = g_h2[r], rcs = g_cs[r];
            pcA = SCBIT(rh0, rh1, rh2, rcs, tA0s, tA1s, tA2s, dAs);
            pcB = SCBIT(rh0, rh1, rh2, rcs, tB0s, tB1s, tB2s, dBs);
        }
        u32 neA = 0, neB = 0;    // R[r0+64]
        if (r0 + 64 < NS) {
            int r = base + r0 + 64;
            float rh0 = g_h0[r], rh1 = g_h1[r], rh2 = g_h2[r], rcs = g_cs[r];
            neA = SCBIT(rh0, rh1, rh2, rcs, tA0s, tA1s, tA2s, dAs);
            neB = SCBIT(rh0, rh1, rh2, rcs, tB0s, tB1s, tB2s, dBs);
        }
        __syncthreads();

        // E bit b = row r0+2(31-b); O bit b = row r0+2(31-b)+1 (LSB newest)
        u32 EA = 0, OA = 0, EB = 0, OB = 0;
#pragma unroll
        for (int j = 0; j < 32; j++) {
            ulonglong2 P0 = sP0[j];
            ulonglong2 P1 = sP1[j];
            u64 qA = f2fma(P0.x, tA0, f2fma(P0.y, tA1, f2fma(P1.x, tA2, f2add(P1.y, dA))));
            u64 qB = f2fma(P0.x, tB0, f2fma(P0.y, tB1, f2fma(P1.x, tB2, f2add(P1.y, dB))));
            u32 lA, hA, lB, hB;
            unpku(qA, lA, hA);
            unpku(qB, lB, hB);
            EA = __funnelshift_l(lA, EA, 1);
            OA = __funnelshift_l(hA, OA, 1);
            EB = __funnelshift_l(lB, EB, 1);
            OB = __funnelshift_l(hB, OB, 1);
        }

        u32 utot = __popc(EA) + __popc(OA) + __popc(EB) + __popc(OB);
        u32 sEA = EA & ~((OA >> 1) | (pcA << 31)) & OA;
        u32 sOA = OA & ~EA & ((EA << 1) | neA);
        u32 sEB = EB & ~((OB >> 1) | (pcB << 31)) & OB;
        u32 sOB = OB & ~EB & ((EB << 1) | neB);
        u32 uvert = __popc(sEA) + __popc(sOA) + __popc(sEB) + __popc(sOB);

#undef SCBIT

        __shared__ unsigned int rt[256], rv[256];
        rt[tid] = utot;
        rv[tid] = uvert;
        __syncthreads();
        for (int o = 128; o > 0; o >>= 1) {
            if (tid < o) { rt[tid] += rt[tid + o]; rv[tid] += rv[tid + o]; }
            __syncthreads();
        }
        if (tid == 0) {
            atomicAdd(&g_total[b], rt[0]);
            atomicAdd(&g_vert[b], rv[0]);
        }
    }

    // ---- last-block final ----
    __threadfence();
    __shared__ unsigned int s_last;
    if (tid == 0) s_last = (atomicAdd(&g_done, 1u) == FUSED_TOTAL - 1u) ? 1u : 0u;
    __syncthreads();
    if (s_last) {
        for (int k = tid; k < NB * 64; k += 256) {
            int bb = k >> 6;
            int j = k & 63;
            float total = (float)g_total[bb];
            float denom = total + 1e-6f;
            float rr = total * (1.0f / ((float)NS * (float)NS));
            float det = (float)g_det[bb] / denom;
            float lam = (float)g_vert[bb] / denom;
            float entr = -total * logf(1.0f + 1e-6f);
            float v = fmaf(rr, w3[j],
                      fmaf(det, w3[64 + j],
                      fmaf(lam, w3[128 + j],
                      fmaf(entr, w3[192 + j], b3[j]))));
            out[k] = fmaxf(v, 0.0f);
        }
    }
}

extern "C" void kernel_launch(void* const* d_in, const int* in_sizes, int n_in,
                              void* d_out, int out_size) {
    const float* x  = (const float*)d_in[0];
    const float* th = (const float*)d_in[1];
    const float* w1 = (const float*)d_in[2];
    const float* b1 = (const float*)d_in[3];
    const float* w2 = (const float*)d_in[4];
    const float* b2 = (const float*)d_in[5];
    const float* w3 = (const float*)d_in[6];
    const float* b3 = (const float*)d_in[7];
    float* out = (float*)d_out;

    k_embed<<<512, 256>>>(x, w1, b1, w2, b2);
    k_max<<<dim3(80, NB), 256>>>();
    k_fused<<<dim3(FUSED_BLOCKS_X, NB), 256>>>(th, w3, b3, out);
}